// round 3
// baseline (speedup 1.0000x reference)
#include <cuda_runtime.h>

#define D 128
#define C 64
#define EPSF 1e-5f

// Scratch (device globals — no allocations allowed)
__device__ float g_protoSum[C * D];
__device__ float g_counts[C];
__device__ float g_protoAdj[C * D];   // prototype - EPS, so t = x - protoAdj = diff + EPS

// ---------------------------------------------------------------------------
// Kernel 0: zero scratch + output
// ---------------------------------------------------------------------------
__global__ void k_zero(float* out) {
    int t = blockIdx.x * blockDim.x + threadIdx.x;
    int stride = gridDim.x * blockDim.x;
    for (int i = t; i < C * D; i += stride) g_protoSum[i] = 0.0f;
    if (t < C) g_counts[t] = 0.0f;
    if (t == 0) out[0] = 0.0f;
}

// ---------------------------------------------------------------------------
// Kernel 1: segment-sum of support rows into prototype sums (global RED.ADD)
// one thread per (row, dim) element -> coalesced loads, spread atomics
// ---------------------------------------------------------------------------
__global__ void k_accum(const float* __restrict__ x,
                        const int* __restrict__ y,
                        int m) {
    int gid = blockIdx.x * blockDim.x + threadIdx.x;
    if (gid >= m * D) return;
    int i = gid >> 7;       // row (D == 128)
    int j = gid & (D - 1);  // dim
    int c = y[i];
    atomicAdd(&g_protoSum[c * D + j], x[gid]);
    if (j == 0) atomicAdd(&g_counts[c], 1.0f);
}

// ---------------------------------------------------------------------------
// Kernel 2: finalize prototypes: proto/count' - EPS
// ---------------------------------------------------------------------------
__global__ void k_proto() {
    int gid = blockIdx.x * blockDim.x + threadIdx.x;
    if (gid >= C * D) return;
    float cnt = g_counts[gid >> 7];
    cnt += (cnt < 0.01f) ? 1.0f : 0.0f;
    g_protoAdj[gid] = g_protoSum[gid] / cnt - EPSF;
}

// ---------------------------------------------------------------------------
// Kernel 3: distances + log_softmax + NLL
// block = 256 threads = 64 targets x 4 class-groups (16 classes each)
// shared: xs[64][132] (padded, conflict-free), ps[64][128], sdist[64][65]
// ---------------------------------------------------------------------------
#define XS_STRIDE 132
#define SD_STRIDE 65

extern __shared__ float smem[];

__global__ __launch_bounds__(256) void k_loss(const float* __restrict__ x,
                                              const int* __restrict__ y,
                                              float* __restrict__ out,
                                              int m) {
    float* xs    = smem;                        // 64 * 132
    float* ps    = xs + 64 * XS_STRIDE;         // 64 * 128
    float* sdist = ps + C * D;                  // 64 * 65
    __shared__ float red[64];

    int tid = threadIdx.x;
    int i0  = blockIdx.x * 64;

    // ---- load x target tile (64 rows x 128), coalesced float4 ----
    const float4* xg = (const float4*)(x + (size_t)(m + i0) * D);
    for (int idx = tid; idx < 64 * (D / 4); idx += 256) {
        int r  = idx >> 5;      // D/4 == 32
        int c4 = idx & 31;
        float4 v = xg[r * (D / 4) + c4];
        *(float4*)&xs[r * XS_STRIDE + c4 * 4] = v;
    }
    // ---- load (prototype - EPS) tile ----
    const float4* pg = (const float4*)g_protoAdj;
    float4* ps4 = (float4*)ps;
    for (int idx = tid; idx < C * D / 4; idx += 256) {
        ps4[idx] = pg[idx];
    }
    __syncthreads();

    int tgt = tid & 63;
    int cg  = tid >> 6;             // uniform within a warp -> p loads broadcast
    const float4* xrow  = (const float4*)&xs[tgt * XS_STRIDE];
    const float*  pbase = &ps[cg * 16 * D];

    float acc[16];
#pragma unroll
    for (int k = 0; k < 16; k++) acc[k] = 0.0f;

    for (int j4 = 0; j4 < D / 4; j4++) {
        float4 xv = xrow[j4];
#pragma unroll
        for (int cc = 0; cc < 16; cc++) {
            float4 pv = *(const float4*)&pbase[cc * D + j4 * 4];
            float t0 = xv.x - pv.x;
            float t1 = xv.y - pv.y;
            float t2 = xv.z - pv.z;
            float t3 = xv.w - pv.w;
            float a = acc[cc];
            a = fmaf(t0, fabsf(t0), a);   // sign(t) * t^2, sign via |t| operand
            a = fmaf(t1, fabsf(t1), a);
            a = fmaf(t2, fabsf(t2), a);
            a = fmaf(t3, fabsf(t3), a);
            acc[cc] = a;
        }
    }

#pragma unroll
    for (int cc = 0; cc < 16; cc++)
        sdist[tgt * SD_STRIDE + cg * 16 + cc] = acc[cc] * (-1.0f / (float)D);

    __syncthreads();

    // ---- log-softmax + NLL per target (64 threads) ----
    if (tid < 64) {
        const float* dr = &sdist[tid * SD_STRIDE];
        float mx = -1e30f;
#pragma unroll 8
        for (int k = 0; k < C; k++) mx = fmaxf(mx, dr[k]);
        float se = 0.0f;
#pragma unroll 8
        for (int k = 0; k < C; k++) se += __expf(dr[k] - mx);
        int yc = y[m + i0 + tid];
        red[tid] = -(dr[yc] - mx - __logf(se));
    }
    __syncthreads();

    if (tid == 0) {
        float s = 0.0f;
#pragma unroll 8
        for (int k = 0; k < 64; k++) s += red[k];
        atomicAdd(out, s / (float)m);
    }
}

// ---------------------------------------------------------------------------
// launch
// ---------------------------------------------------------------------------
extern "C" void kernel_launch(void* const* d_in, const int* in_sizes, int n_in,
                              void* d_out, int out_size) {
    const float* x = (const float*)d_in[0];
    const int*   y = (const int*)d_in[1];
    int n = in_sizes[1];     // number of rows (y element count)
    int m = n / 2;
    float* out = (float*)d_out;

    k_zero<<<32, 256>>>(out);
    k_accum<<<(m * D + 255) / 256, 256>>>(x, y, m);
    k_proto<<<(C * D + 255) / 256, 256>>>();

    size_t smembytes = (size_t)(64 * XS_STRIDE + C * D + 64 * SD_STRIDE) * sizeof(float);
    cudaFuncSetAttribute(k_loss, cudaFuncAttributeMaxDynamicSharedMemorySize,
                         (int)smembytes);
    k_loss<<<m / 64, 256, smembytes>>>(x, y, out, m);
}